// round 2
// baseline (speedup 1.0000x reference)
#include <cuda_runtime.h>
#include <cstdint>
#include <cstddef>

// Problem constants: S=1024, B=4, E=1024, H=16, D=64
#define S_LEN   1024
#define BATCH   4
#define NHEADS  16
#define DHEAD   64
#define NBH     64          // BATCH*NHEADS
#define NROWS   4096        // S*B
#define EMB     1024

typedef unsigned long long ull;

// ---------------- scratch (device globals; no allocation allowed) ----------
__device__ float g_q[(size_t)NBH * S_LEN * DHEAD];     // [bh][s][d], q pre-scaled by D^-0.5
__device__ float g_k[(size_t)NBH * S_LEN * DHEAD];
__device__ float g_v[(size_t)NBH * S_LEN * DHEAD];
__device__ float g_attn[(size_t)NROWS * EMB];          // [s*B+b][h*64+d]

// ---------------- packed f32x2 helpers (B300: FFMA2 is double-rate) --------
__device__ __forceinline__ ull pk2(float x, float y) {
    ull r;
    asm("mov.b64 %0, {%1, %2};" : "=l"(r) : "r"(__float_as_uint(x)), "r"(__float_as_uint(y)));
    return r;
}
__device__ __forceinline__ void upk2(ull v, float& x, float& y) {
    unsigned int a, b;
    asm("mov.b64 {%0, %1}, %2;" : "=r"(a), "=r"(b) : "l"(v));
    x = __uint_as_float(a); y = __uint_as_float(b);
}
__device__ __forceinline__ ull ffma2(ull a, ull b, ull c) {
    ull d;
    asm("fma.rn.f32x2 %0, %1, %2, %3;" : "=l"(d) : "l"(a), "l"(b), "l"(c));
    return d;
}
__device__ __forceinline__ ull fmul2(ull a, ull b) {
    ull d;
    asm("mul.rn.f32x2 %0, %1, %2;" : "=l"(d) : "l"(a), "l"(b));
    return d;
}

// ===========================================================================
// Generic NT SGEMM: C[m][n] = sum_k A[m][k] * Bw[n][k] + bias[n]
// A: (M x 1024) row-major, Bw: (N x 1024) row-major. Tile 128x128, BK=16,
// 256 threads, 8x8 microtile, f32x2 packed FMA.
// MODE 0: A = x, write routed to g_q/g_k/g_v (QKV projection, q scaled 0.125)
// MODE 1: A = g_attn, write C = out (output projection)
// ===========================================================================
template <int MODE>
__global__ __launch_bounds__(256)
void sgemm_nt(const float* __restrict__ A, const float* __restrict__ Bw,
              const float* __restrict__ bias, float* __restrict__ Cout, int N)
{
    __shared__ float As[16][132];   // [k][m], pad 132 to cut STS conflicts
    __shared__ float Bs[16][132];   // [k][n]

    const int K = 1024;
    const int tid = threadIdx.x;
    const int m0 = blockIdx.y * 128;
    const int n0 = blockIdx.x * 128;
    const int tr = tid >> 4;        // 0..15 -> rows tr*8 .. tr*8+7
    const int tc = tid & 15;        // 0..15 -> cols {tc*4..+4} U {64+tc*4..+4}

    const float* Aptr = (MODE == 1) ? g_attn : A;

    ull acc[8][4];
#pragma unroll
    for (int i = 0; i < 8; i++)
#pragma unroll
        for (int j = 0; j < 4; j++) acc[i][j] = 0ull;

    const int lrow = tid >> 2;        // 0..63
    const int lk   = (tid & 3) * 4;   // 0,4,8,12

    for (int k0 = 0; k0 < K; k0 += 16) {
#pragma unroll
        for (int half = 0; half < 2; half++) {
            int row = lrow + half * 64;
            float4 av = __ldg((const float4*)(Aptr + (size_t)(m0 + row) * K + k0 + lk));
            float4 bv = __ldg((const float4*)(Bw   + (size_t)(n0 + row) * K + k0 + lk));
            As[lk + 0][row] = av.x; As[lk + 1][row] = av.y;
            As[lk + 2][row] = av.z; As[lk + 3][row] = av.w;
            Bs[lk + 0][row] = bv.x; Bs[lk + 1][row] = bv.y;
            Bs[lk + 2][row] = bv.z; Bs[lk + 3][row] = bv.w;
        }
        __syncthreads();

#pragma unroll
        for (int k = 0; k < 16; k++) {
            float4 a0 = *(const float4*)&As[k][tr * 8];
            float4 a1 = *(const float4*)&As[k][tr * 8 + 4];
            float4 b0 = *(const float4*)&Bs[k][tc * 4];
            float4 b1 = *(const float4*)&Bs[k][64 + tc * 4];
            ull b2[4] = { pk2(b0.x, b0.y), pk2(b0.z, b0.w),
                          pk2(b1.x, b1.y), pk2(b1.z, b1.w) };
            float av8[8] = { a0.x, a0.y, a0.z, a0.w, a1.x, a1.y, a1.z, a1.w };
#pragma unroll
            for (int i = 0; i < 8; i++) {
                ull a2 = pk2(av8[i], av8[i]);
#pragma unroll
                for (int j = 0; j < 4; j++) acc[i][j] = ffma2(a2, b2[j], acc[i][j]);
            }
        }
        __syncthreads();
    }

    // epilogue
#pragma unroll
    for (int i = 0; i < 8; i++) {
        int m = m0 + tr * 8 + i;
#pragma unroll
        for (int hf = 0; hf < 2; hf++) {
            int c0 = n0 + hf * 64 + tc * 4;
            float4 v;
            upk2(acc[i][hf * 2 + 0], v.x, v.y);
            upk2(acc[i][hf * 2 + 1], v.z, v.w);
            float4 bb = __ldg((const float4*)(bias + c0));
            v.x += bb.x; v.y += bb.y; v.z += bb.z; v.w += bb.w;
            if (MODE == 0) {
                // route into q/k/v head-layout.  c0 % 4 == 0 and all q/k/v
                // boundaries are multiples of 64, so a float4 never straddles.
                int s = m >> 2, b = m & 3;
                int h = c0 / 192, t = c0 % 192;
                size_t base = ((size_t)(b * NHEADS + h) * S_LEN + s) * DHEAD;
                if (t < 64) {
                    v.x *= 0.125f; v.y *= 0.125f; v.z *= 0.125f; v.w *= 0.125f;
                    *(float4*)(g_q + base + t) = v;
                } else if (t < 128) {
                    *(float4*)(g_k + base + (t - 64)) = v;
                } else {
                    *(float4*)(g_v + base + (t - 128)) = v;
                }
            } else {
                *(float4*)(Cout + (size_t)m * N + c0) = v;
            }
        }
    }
}

// ===========================================================================
// Fused attention: per (head, 64-query tile) block.
//   scores = q.kT (+bias, mask) -> online softmax_1 -> p = e*mul -> O += p.V
// softmax_1: denom = exp(-m) + sum(exp(s-m)); running max init 0 makes the
// phantom "+1" exact: denom_final = exp(-m_final) + l_final.
// Shared = exactly 48KB: Qs(16K) + Vs(16K) + union(Ks,Ps)(16K).
// key_padding_mask arrives as int32 (bool_ widened by the harness dtype set).
// ===========================================================================
__global__ __launch_bounds__(256)
void attn_kernel(const float* __restrict__ abias, const float* __restrict__ amul,
                 const int* __restrict__ kpm)
{
    __shared__ float Qs[64 * 64];   // [d][q]
    __shared__ float Vs[64 * 64];   // [kc][d]
    __shared__ float KP[64 * 64];   // phase1: Ks[d][kc]; phase2: Ps[qr][kc]

    const int tid = threadIdx.x;
    const int ty = tid >> 4;        // 0..15 -> q rows ty*4..+4
    const int tx = tid & 15;        // 0..15 -> kc/d cols tx*4..+4
    const int bh = blockIdx.y;
    const int q0 = blockIdx.x * 64;
    const int b = bh >> 4, h = bh & 15;

    const float* qg = g_q + (size_t)bh * (S_LEN * DHEAD);
    const float* kg = g_k + (size_t)bh * (S_LEN * DHEAD);
    const float* vg = g_v + (size_t)bh * (S_LEN * DHEAD);
    const int* kp = kpm + b * S_LEN;

    // load Q tile transposed: Qs[d][q] = qg[(q0+q)*64 + d]
#pragma unroll
    for (int it = 0; it < 4; it++) {
        int idx = tid + 256 * it;        // float4 units, 0..1023
        int q = idx & 63;
        int d4 = idx >> 6;               // 0..15
        float4 v = __ldg((const float4*)(qg + (size_t)(q0 + q) * DHEAD + d4 * 4));
        Qs[(d4 * 4 + 0) * 64 + q] = v.x;
        Qs[(d4 * 4 + 1) * 64 + q] = v.y;
        Qs[(d4 * 4 + 2) * 64 + q] = v.z;
        Qs[(d4 * 4 + 3) * 64 + q] = v.w;
    }

    ull o2[4][2];
#pragma unroll
    for (int i = 0; i < 4; i++) { o2[i][0] = 0ull; o2[i][1] = 0ull; }
    float mrow[4] = {0.f, 0.f, 0.f, 0.f};   // running max (phantom 0 included)
    float lsum[4] = {0.f, 0.f, 0.f, 0.f};   // per-lane partial sum of e

    for (int k0 = 0; k0 < S_LEN; k0 += 64) {
        __syncthreads();   // protect KP/Vs from prior-iteration readers (and Qs on iter 0)

        // load K chunk transposed into KP, V chunk direct into Vs
#pragma unroll
        for (int it = 0; it < 4; it++) {
            int idx = tid + 256 * it;
            int kcq = idx & 63;
            int d4 = idx >> 6;
            float4 kv = __ldg((const float4*)(kg + (size_t)(k0 + kcq) * DHEAD + d4 * 4));
            KP[(d4 * 4 + 0) * 64 + kcq] = kv.x;
            KP[(d4 * 4 + 1) * 64 + kcq] = kv.y;
            KP[(d4 * 4 + 2) * 64 + kcq] = kv.z;
            KP[(d4 * 4 + 3) * 64 + kcq] = kv.w;
            int kc = idx >> 4;
            int dv4 = idx & 15;
            float4 vv = __ldg((const float4*)(vg + (size_t)(k0 + kc) * DHEAD + dv4 * 4));
            *(float4*)(Vs + kc * 64 + dv4 * 4) = vv;
        }
        __syncthreads();

        // ---- scores: s[i][j] = sum_d Qs[d][ty*4+i] * Ks[d][tx*4+j]
        ull s2[4][2];
#pragma unroll
        for (int i = 0; i < 4; i++) { s2[i][0] = 0ull; s2[i][1] = 0ull; }
#pragma unroll 8
        for (int d = 0; d < 64; d++) {
            float4 qa = *(const float4*)(Qs + d * 64 + ty * 4);
            float4 kb = *(const float4*)(KP + d * 64 + tx * 4);
            ull kb0 = pk2(kb.x, kb.y), kb1 = pk2(kb.z, kb.w);
            float qv[4] = { qa.x, qa.y, qa.z, qa.w };
#pragma unroll
            for (int i = 0; i < 4; i++) {
                ull a2 = pk2(qv[i], qv[i]);
                s2[i][0] = ffma2(a2, kb0, s2[i][0]);
                s2[i][1] = ffma2(a2, kb1, s2[i][1]);
            }
        }
        float sc[4][4];
#pragma unroll
        for (int i = 0; i < 4; i++) {
            upk2(s2[i][0], sc[i][0], sc[i][1]);
            upk2(s2[i][1], sc[i][2], sc[i][3]);
        }

        // ---- bias + mask + online softmax_1 update
        int4 mk = *(const int4*)(kp + k0 + tx * 4);
        float4 pw[4];
        float alpha[4];
#pragma unroll
        for (int i = 0; i < 4; i++) {
            int qr = q0 + ty * 4 + i;
            size_t off = ((size_t)bh * S_LEN + qr) * S_LEN + k0 + tx * 4;
            float4 bb = __ldg((const float4*)(abias + off));
            float4 mm = __ldg((const float4*)(amul + off));
            sc[i][0] += bb.x; sc[i][1] += bb.y; sc[i][2] += bb.z; sc[i][3] += bb.w;
            if (mk.x) sc[i][0] = -1e30f;
            if (mk.y) sc[i][1] = -1e30f;
            if (mk.z) sc[i][2] = -1e30f;
            if (mk.w) sc[i][3] = -1e30f;

            float cm = fmaxf(fmaxf(sc[i][0], sc[i][1]), fmaxf(sc[i][2], sc[i][3]));
            cm = fmaxf(cm, __shfl_xor_sync(0xffffffffu, cm, 8, 16));
            cm = fmaxf(cm, __shfl_xor_sync(0xffffffffu, cm, 4, 16));
            cm = fmaxf(cm, __shfl_xor_sync(0xffffffffu, cm, 2, 16));
            cm = fmaxf(cm, __shfl_xor_sync(0xffffffffu, cm, 1, 16));

            float nm = fmaxf(mrow[i], cm);
            alpha[i] = __expf(mrow[i] - nm);
            mrow[i] = nm;

            float e0 = __expf(sc[i][0] - nm);
            float e1 = __expf(sc[i][1] - nm);
            float e2 = __expf(sc[i][2] - nm);
            float e3 = __expf(sc[i][3] - nm);
            lsum[i] = lsum[i] * alpha[i] + (e0 + e1 + e2 + e3);
            pw[i] = make_float4(e0 * mm.x, e1 * mm.y, e2 * mm.z, e3 * mm.w);
        }
        __syncthreads();   // everyone done reading Ks

        // ---- write Ps (reuse KP) and rescale O
#pragma unroll
        for (int i = 0; i < 4; i++) {
            *(float4*)(KP + (ty * 4 + i) * 64 + tx * 4) = pw[i];
            ull a2 = pk2(alpha[i], alpha[i]);
            o2[i][0] = fmul2(o2[i][0], a2);
            o2[i][1] = fmul2(o2[i][1], a2);
        }
        __syncthreads();

        // ---- O[qr][d] += sum_kc Ps[qr][kc] * Vs[kc][d]
#pragma unroll 4
        for (int kc4 = 0; kc4 < 16; kc4++) {
            float4 pr[4];
#pragma unroll
            for (int i = 0; i < 4; i++)
                pr[i] = *(const float4*)(KP + (ty * 4 + i) * 64 + kc4 * 4);
#pragma unroll
            for (int u = 0; u < 4; u++) {
                float4 vv = *(const float4*)(Vs + (kc4 * 4 + u) * 64 + tx * 4);
                ull v0 = pk2(vv.x, vv.y), v1 = pk2(vv.z, vv.w);
#pragma unroll
                for (int i = 0; i < 4; i++) {
                    float p = (&pr[i].x)[u];
                    ull p2 = pk2(p, p);
                    o2[i][0] = ffma2(p2, v0, o2[i][0]);
                    o2[i][1] = ffma2(p2, v1, o2[i][1]);
                }
            }
        }
    }

    // ---- finalize: denom = exp(-m) + sum(e); write g_attn
#pragma unroll
    for (int i = 0; i < 4; i++) {
        float l = lsum[i];
        l += __shfl_xor_sync(0xffffffffu, l, 8, 16);
        l += __shfl_xor_sync(0xffffffffu, l, 4, 16);
        l += __shfl_xor_sync(0xffffffffu, l, 2, 16);
        l += __shfl_xor_sync(0xffffffffu, l, 1, 16);
        float denom = __expf(-mrow[i]) + l;
        float inv = 1.0f / denom;
        float4 ov;
        upk2(o2[i][0], ov.x, ov.y);
        upk2(o2[i][1], ov.z, ov.w);
        ov.x *= inv; ov.y *= inv; ov.z *= inv; ov.w *= inv;
        int r = (q0 + ty * 4 + i) * BATCH + b;
        *(float4*)(g_attn + (size_t)r * EMB + h * DHEAD + tx * 4) = ov;
    }
}

// ===========================================================================
extern "C" void kernel_launch(void* const* d_in, const int* in_sizes, int n_in,
                              void* d_out, int out_size)
{
    const float* x     = (const float*)d_in[0];
    const float* ab    = (const float*)d_in[1];
    const float* abm   = (const float*)d_in[2];
    const int*   kpm   = (const int*)d_in[3];
    const float* W_in  = (const float*)d_in[4];
    const float* b_in  = (const float*)d_in[5];
    const float* W_out = (const float*)d_in[6];
    const float* b_out = (const float*)d_in[7];
    float* out = (float*)d_out;

    // 1) QKV projection: (4096 x 1024) @ (3072 x 1024)^T -> routed q/k/v
    sgemm_nt<0><<<dim3(24, 32), 256>>>(x, W_in, b_in, nullptr, 3 * EMB);
    // 2) fused attention -> g_attn
    attn_kernel<<<dim3(16, 64), 256>>>(ab, abm, kpm);
    // 3) output projection: (4096 x 1024) @ (1024 x 1024)^T -> out
    sgemm_nt<1><<<dim3(8, 32), 256>>>(nullptr, W_out, b_out, out, EMB);
}

// round 4
// speedup vs baseline: 1.4505x; 1.4505x over previous
#include <cuda_runtime.h>
#include <cuda_bf16.h>
#include <cstdint>
#include <cstddef>

// Problem constants: S=1024, B=4, E=1024, H=16, D=64
#define S_LEN   1024
#define BATCH   4
#define NHEADS  16
#define DHEAD   64
#define NBH     64          // BATCH*NHEADS
#define NROWS   4096        // S*B
#define EMB     1024

typedef unsigned long long ull;

// ---------------- scratch (device globals; no allocation allowed) ----------
__device__ float g_q[(size_t)NBH * S_LEN * DHEAD];     // [bh][s][d], q pre-scaled
__device__ float g_k[(size_t)NBH * S_LEN * DHEAD];
__device__ float g_v[(size_t)NBH * S_LEN * DHEAD];
__device__ float g_attn[(size_t)NROWS * EMB];          // [s*B+b][h*64+d]

// Split-bf16 K-tripled operands (K_eff = 3072):
//   A3 = [Ahi | Ahi | Alo]   (rows x 3072)
//   W3 = [Whi | Wlo | Whi]   (rows x 3072)
// dot(A3,W3) = Ahi.Whi + Ahi.Wlo + Alo.Whi  (exact product minus tiny lo.lo)
__device__ __nv_bfloat16 g_a3   [(size_t)4096 * 3072];
__device__ __nv_bfloat16 g_w3in [(size_t)3072 * 3072];
__device__ __nv_bfloat16 g_w3out[(size_t)1024 * 3072];

// ---------------- packed f32x2 helpers (attention kernel) ------------------
__device__ __forceinline__ ull pk2(float x, float y) {
    ull r;
    asm("mov.b64 %0, {%1, %2};" : "=l"(r) : "r"(__float_as_uint(x)), "r"(__float_as_uint(y)));
    return r;
}
__device__ __forceinline__ void upk2(ull v, float& x, float& y) {
    unsigned int a, b;
    asm("mov.b64 {%0, %1}, %2;" : "=r"(a), "=r"(b) : "l"(v));
    x = __uint_as_float(a); y = __uint_as_float(b);
}
__device__ __forceinline__ ull ffma2(ull a, ull b, ull c) {
    ull d;
    asm("fma.rn.f32x2 %0, %1, %2, %3;" : "=l"(d) : "l"(a), "l"(b), "l"(c));
    return d;
}
__device__ __forceinline__ ull fmul2(ull a, ull b) {
    ull d;
    asm("mul.rn.f32x2 %0, %1, %2;" : "=l"(d) : "l"(a), "l"(b));
    return d;
}

// ---------------- baseline-PTX async-copy / ldmatrix / mma -----------------
__device__ __forceinline__ uint32_t smem_u32(const void* p) {
    uint32_t a;
    asm("{ .reg .u64 t; cvta.to.shared.u64 t, %1; cvt.u32.u64 %0, t; }" : "=r"(a) : "l"(p));
    return a;
}
__device__ __forceinline__ void cp_async16(uint32_t saddr, const void* g) {
    asm volatile("cp.async.cg.shared.global [%0], [%1], 16;" :: "r"(saddr), "l"(g));
}
#define CP_COMMIT() asm volatile("cp.async.commit_group;" ::: "memory")
#define CP_WAIT0()  asm volatile("cp.async.wait_group 0;" ::: "memory")

__device__ __forceinline__ void ldsm_x4(uint32_t& r0, uint32_t& r1, uint32_t& r2, uint32_t& r3,
                                        uint32_t addr) {
    asm volatile("ldmatrix.sync.aligned.m8n8.x4.shared.b16 {%0,%1,%2,%3}, [%4];"
                 : "=r"(r0), "=r"(r1), "=r"(r2), "=r"(r3) : "r"(addr));
}
__device__ __forceinline__ void mma16816(float* c, const uint32_t* a, const uint32_t* b) {
    asm volatile("mma.sync.aligned.m16n8k16.row.col.f32.bf16.bf16.f32 "
                 "{%0,%1,%2,%3}, {%4,%5,%6,%7}, {%8,%9}, {%0,%1,%2,%3};"
                 : "+f"(c[0]), "+f"(c[1]), "+f"(c[2]), "+f"(c[3])
                 : "r"(a[0]), "r"(a[1]), "r"(a[2]), "r"(a[3]), "r"(b[0]), "r"(b[1]));
}

__device__ __forceinline__ unsigned pack_bf(__nv_bfloat16 a, __nv_bfloat16 b) {
    return (unsigned)__bfloat16_as_ushort(a) | ((unsigned)__bfloat16_as_ushort(b) << 16);
}

// ===========================================================================
// Split conversion: src fp32 [rows x 1024] -> dst bf16 [rows x 3072].
// STYLE 0 (activations): [hi | hi | lo].  STYLE 1 (weights): [hi | lo | hi].
// Grid sized exactly: rows*512 pair-threads.
// ===========================================================================
template <int STYLE>
__global__ void split_kernel(const float* __restrict__ src, __nv_bfloat16* __restrict__ dst)
{
    int idx = blockIdx.x * 256 + threadIdx.x;       // one k-pair
    int r = idx >> 9, kp = idx & 511;
    float2 v = *(const float2*)(src + (size_t)r * 1024 + kp * 2);
    __nv_bfloat16 h0 = __float2bfloat16(v.x), h1 = __float2bfloat16(v.y);
    unsigned hp = pack_bf(h0, h1);
    unsigned lp = pack_bf(__float2bfloat16(v.x - __bfloat162float(h0)),
                          __float2bfloat16(v.y - __bfloat162float(h1)));
    size_t base = (size_t)r * 3072 + kp * 2;
    *(unsigned*)(dst + base)        = hp;
    *(unsigned*)(dst + base + 1024) = (STYLE == 0) ? hp : lp;
    *(unsigned*)(dst + base + 2048) = (STYLE == 0) ? lp : hp;
}

// ===========================================================================
// mma.sync bf16 GEMM over K_eff=3072: C[m][n] = A3[m,:].W3[n,:] + bias[n].
// Tile 128x128, BK=32, 256 threads (8 warps as 2m x 4n), warp tile 64x32,
// double-buffered cp.async, XOR-swizzled SMEM (conflict-free ldmatrix).
// MODE 0: A3 = split(x), W3 = split(W_in); epilogue routes q/k/v (q*0.125).
// MODE 1: A3 = split(g_attn), W3 = split(W_out); epilogue writes Cout.
// ===========================================================================
template <int MODE>
__global__ __launch_bounds__(256, 2)
void gemm_ms(const float* __restrict__ bias, float* __restrict__ Cout)
{
    constexpr int KE = 3072;
    __shared__ __align__(16) __nv_bfloat16 sA[2][128 * 32];
    __shared__ __align__(16) __nv_bfloat16 sB[2][128 * 32];

    const __nv_bfloat16* __restrict__ A3 = g_a3;
    const __nv_bfloat16* __restrict__ B3 = (MODE == 0) ? g_w3in : g_w3out;

    const int tid = threadIdx.x;
    const int wid = tid >> 5, lane = tid & 31;
    const int wm = wid & 1, wn = wid >> 1;
    const int m0 = blockIdx.y * 128, n0 = blockIdx.x * 128;

    float c[4][4][4];
#pragma unroll
    for (int i = 0; i < 4; i++)
#pragma unroll
        for (int j = 0; j < 4; j++)
#pragma unroll
            for (int r = 0; r < 4; r++) c[i][j][r] = 0.f;

    // stage loader: 512 granules (16B) per matrix; 2 per thread per matrix.
    // swizzle: granule' = granule ^ ((row>>1)&3)
    auto loadStage = [&](int st, int k0) {
        uint32_t baseA = smem_u32(&sA[st][0]);
        uint32_t baseB = smem_u32(&sB[st][0]);
#pragma unroll
        for (int h = 0; h < 2; h++) {
            int g = tid + 256 * h;
            int row = g >> 2, gc = g & 3;
            int sw = gc ^ ((row >> 1) & 3);
            cp_async16(baseA + row * 64 + sw * 16, A3 + (size_t)(m0 + row) * KE + k0 + gc * 8);
            cp_async16(baseB + row * 64 + sw * 16, B3 + (size_t)(n0 + row) * KE + k0 + gc * 8);
        }
    };

    loadStage(0, 0);
    CP_COMMIT();

    for (int s = 0; s < KE / 32; s++) {
        CP_WAIT0();
        __syncthreads();
        if (s + 1 < KE / 32) {
            loadStage((s + 1) & 1, (s + 1) * 32);
            CP_COMMIT();
        }
        const int st = s & 1;
        const uint32_t baseA = smem_u32(&sA[st][0]);
        const uint32_t baseB = smem_u32(&sB[st][0]);

#pragma unroll
        for (int j = 0; j < 2; j++) {          // two k16 sub-steps
            uint32_t a[4][4];
#pragma unroll
            for (int mf = 0; mf < 4; mf++) {
                int row = wm * 64 + mf * 16 + (lane & 15);
                int g = j * 2 + (lane >> 4);
                int sw = g ^ ((row >> 1) & 3);
                ldsm_x4(a[mf][0], a[mf][1], a[mf][2], a[mf][3], baseA + row * 64 + sw * 16);
            }
            uint32_t b[4][2];
#pragma unroll
            for (int p = 0; p < 2; p++) {      // pair of n8 frags per ldmatrix.x4
                int row = wn * 32 + p * 16 + (lane & 7) + ((lane >> 4) << 3);
                int g = j * 2 + ((lane >> 3) & 1);
                int sw = g ^ ((row >> 1) & 3);
                uint32_t r0, r1, r2, r3;
                ldsm_x4(r0, r1, r2, r3, baseB + row * 64 + sw * 16);
                b[p * 2][0] = r0; b[p * 2][1] = r1;
                b[p * 2 + 1][0] = r2; b[p * 2 + 1][1] = r3;
            }
#pragma unroll
            for (int mf = 0; mf < 4; mf++)
#pragma unroll
                for (int nf = 0; nf < 4; nf++)
                    mma16816(c[mf][nf], a[mf], b[nf]);
        }
        __syncthreads();
    }

    // ---- epilogue: thread holds rows {t/4, t/4+8}, col pair (t%4)*2
#pragma unroll
    for (int mf = 0; mf < 4; mf++) {
#pragma unroll
        for (int nf = 0; nf < 4; nf++) {
            int n = n0 + wn * 32 + nf * 8 + (lane & 3) * 2;
            float2 bb = *(const float2*)(bias + n);
#pragma unroll
            for (int half = 0; half < 2; half++) {
                int m = m0 + wm * 64 + mf * 16 + (lane >> 2) + half * 8;
                float vx = c[mf][nf][half * 2 + 0] + bb.x;
                float vy = c[mf][nf][half * 2 + 1] + bb.y;
                if (MODE == 0) {
                    int sI = m >> 2, bI = m & 3;
                    int h = n / 192, t = n % 192;
                    size_t base = ((size_t)(bI * NHEADS + h) * S_LEN + sI) * DHEAD;
                    if (t < 64) {
                        *(float2*)(g_q + base + t) = make_float2(vx * 0.125f, vy * 0.125f);
                    } else if (t < 128) {
                        *(float2*)(g_k + base + (t - 64)) = make_float2(vx, vy);
                    } else {
                        *(float2*)(g_v + base + (t - 128)) = make_float2(vx, vy);
                    }
                } else {
                    *(float2*)(Cout + (size_t)m * EMB + n) = make_float2(vx, vy);
                }
            }
        }
    }
}

// ===========================================================================
// Fused attention (UNCHANGED from passing R2 kernel, 1312us run).
// ===========================================================================
__global__ __launch_bounds__(256)
void attn_kernel(const float* __restrict__ abias, const float* __restrict__ amul,
                 const int* __restrict__ kpm)
{
    __shared__ float Qs[64 * 64];   // [d][q]
    __shared__ float Vs[64 * 64];   // [kc][d]
    __shared__ float KP[64 * 64];   // phase1: Ks[d][kc]; phase2: Ps[qr][kc]

    const int tid = threadIdx.x;
    const int ty = tid >> 4;
    const int tx = tid & 15;
    const int bh = blockIdx.y;
    const int q0 = blockIdx.x * 64;
    const int b = bh >> 4, h = bh & 15;

    const float* qg = g_q + (size_t)bh * (S_LEN * DHEAD);
    const float* kg = g_k + (size_t)bh * (S_LEN * DHEAD);
    const float* vg = g_v + (size_t)bh * (S_LEN * DHEAD);
    const int* kp = kpm + b * S_LEN;

#pragma unroll
    for (int it = 0; it < 4; it++) {
        int idx = tid + 256 * it;
        int q = idx & 63;
        int d4 = idx >> 6;
        float4 v = __ldg((const float4*)(qg + (size_t)(q0 + q) * DHEAD + d4 * 4));
        Qs[(d4 * 4 + 0) * 64 + q] = v.x;
        Qs[(d4 * 4 + 1) * 64 + q] = v.y;
        Qs[(d4 * 4 + 2) * 64 + q] = v.z;
        Qs[(d4 * 4 + 3) * 64 + q] = v.w;
    }

    ull o2[4][2];
#pragma unroll
    for (int i = 0; i < 4; i++) { o2[i][0] = 0ull; o2[i][1] = 0ull; }
    float mrow[4] = {0.f, 0.f, 0.f, 0.f};
    float lsum[4] = {0.f, 0.f, 0.f, 0.f};

    for (int k0 = 0; k0 < S_LEN; k0 += 64) {
        __syncthreads();

#pragma unroll
        for (int it = 0; it < 4; it++) {
            int idx = tid + 256 * it;
            int kcq = idx & 63;
            int d4 = idx >> 6;
            float4 kv = __ldg((const float4*)(kg + (size_t)(k0 + kcq) * DHEAD + d4 * 4));
            KP[(d4 * 4 + 0) * 64 + kcq] = kv.x;
            KP[(d4 * 4 + 1) * 64 + kcq] = kv.y;
            KP[(d4 * 4 + 2) * 64 + kcq] = kv.z;
            KP[(d4 * 4 + 3) * 64 + kcq] = kv.w;
            int kc = idx >> 4;
            int dv4 = idx & 15;
            float4 vv = __ldg((const float4*)(vg + (size_t)(k0 + kc) * DHEAD + dv4 * 4));
            *(float4*)(Vs + kc * 64 + dv4 * 4) = vv;
        }
        __syncthreads();

        ull s2[4][2];
#pragma unroll
        for (int i = 0; i < 4; i++) { s2[i][0] = 0ull; s2[i][1] = 0ull; }
#pragma unroll 8
        for (int d = 0; d < 64; d++) {
            float4 qa = *(const float4*)(Qs + d * 64 + ty * 4);
            float4 kb = *(const float4*)(KP + d * 64 + tx * 4);
            ull kb0 = pk2(kb.x, kb.y), kb1 = pk2(kb.z, kb.w);
            float qv[4] = { qa.x, qa.y, qa.z, qa.w };
#pragma unroll
            for (int i = 0; i < 4; i++) {
                ull a2 = pk2(qv[i], qv[i]);
                s2[i][0] = ffma2(a2, kb0, s2[i][0]);
                s2[i][1] = ffma2(a2, kb1, s2[i][1]);
            }
        }
        float sc[4][4];
#pragma unroll
        for (int i = 0; i < 4; i++) {
            upk2(s2[i][0], sc[i][0], sc[i][1]);
            upk2(s2[i][1], sc[i][2], sc[i][3]);
        }

        int4 mk = *(const int4*)(kp + k0 + tx * 4);
        float4 pw[4];
        float alpha[4];
#pragma unroll
        for (int i = 0; i < 4; i++) {
            int qr = q0 + ty * 4 + i;
            size_t off = ((size_t)bh * S_LEN + qr) * S_LEN + k0 + tx * 4;
            float4 bb = __ldg((const float4*)(abias + off));
            float4 mm = __ldg((const float4*)(amul + off));
            sc[i][0] += bb.x; sc[i][1] += bb.y; sc[i][2] += bb.z; sc[i][3] += bb.w;
            if (mk.x) sc[i][0] = -1e30f;
            if (mk.y) sc[i][1] = -1e30f;
            if (mk.z) sc[i][2] = -1e30f;
            if (mk.w) sc[i][3] = -1e30f;

            float cm = fmaxf(fmaxf(sc[i][0], sc[i][1]), fmaxf(sc[i][2], sc[i][3]));
            cm = fmaxf(cm, __shfl_xor_sync(0xffffffffu, cm, 8, 16));
            cm = fmaxf(cm, __shfl_xor_sync(0xffffffffu, cm, 4, 16));
            cm = fmaxf(cm, __shfl_xor_sync(0xffffffffu, cm, 2, 16));
            cm = fmaxf(cm, __shfl_xor_sync(0xffffffffu, cm, 1, 16));

            float nm = fmaxf(mrow[i], cm);
            alpha[i] = __expf(mrow[i] - nm);
            mrow[i] = nm;

            float e0 = __expf(sc[i][0] - nm);
            float e1 = __expf(sc[i][1] - nm);
            float e2 = __expf(sc[i][2] - nm);
            float e3 = __expf(sc[i][3] - nm);
            lsum[i] = lsum[i] * alpha[i] + (e0 + e1 + e2 + e3);
            pw[i] = make_float4(e0 * mm.x, e1 * mm.y, e2 * mm.z, e3 * mm.w);
        }
        __syncthreads();

#pragma unroll
        for (int i = 0; i < 4; i++) {
            *(float4*)(KP + (ty * 4 + i) * 64 + tx * 4) = pw[i];
            ull a2 = pk2(alpha[i], alpha[i]);
            o2[i][0] = fmul2(o2[i][0], a2);
            o2[i][1] = fmul2(o2[i][1], a2);
        }
        __syncthreads();

#pragma unroll 4
        for (int kc4 = 0; kc4 < 16; kc4++) {
            float4 pr[4];
#pragma unroll
            for (int i = 0; i < 4; i++)
                pr[i] = *(const float4*)(KP + (ty * 4 + i) * 64 + kc4 * 4);
#pragma unroll
            for (int u = 0; u < 4; u++) {
                float4 vv = *(const float4*)(Vs + (kc4 * 4 + u) * 64 + tx * 4);
                ull v0 = pk2(vv.x, vv.y), v1 = pk2(vv.z, vv.w);
#pragma unroll
                for (int i = 0; i < 4; i++) {
                    float p = (&pr[i].x)[u];
                    ull p2 = pk2(p, p);
                    o2[i][0] = ffma2(p2, v0, o2[i][0]);
                    o2[i][1] = ffma2(p2, v1, o2[i][1]);
                }
            }
        }
    }

#pragma unroll
    for (int i = 0; i < 4; i++) {
        float l = lsum[i];
        l += __shfl_xor_sync(0xffffffffu, l, 8, 16);
        l += __shfl_xor_sync(0xffffffffu, l, 4, 16);
        l += __shfl_xor_sync(0xffffffffu, l, 2, 16);
        l += __shfl_xor_sync(0xffffffffu, l, 1, 16);
        float denom = __expf(-mrow[i]) + l;
        float inv = 1.0f / denom;
        float4 ov;
        upk2(o2[i][0], ov.x, ov.y);
        upk2(o2[i][1], ov.z, ov.w);
        ov.x *= inv; ov.y *= inv; ov.z *= inv; ov.w *= inv;
        int r = (q0 + ty * 4 + i) * BATCH + b;
        *(float4*)(g_attn + (size_t)r * EMB + h * DHEAD + tx * 4) = ov;
    }
}

// ===========================================================================
extern "C" void kernel_launch(void* const* d_in, const int* in_sizes, int n_in,
                              void* d_out, int out_size)
{
    const float* x     = (const float*)d_in[0];
    const float* ab    = (const float*)d_in[1];
    const float* abm   = (const float*)d_in[2];
    const int*   kpm   = (const int*)d_in[3];
    const float* W_in  = (const float*)d_in[4];
    const float* b_in  = (const float*)d_in[5];
    const float* W_out = (const float*)d_in[6];
    const float* b_out = (const float*)d_in[7];
    float* out = (float*)d_out;

    __nv_bfloat16 *a3, *w3in, *w3out;
    float* attn_src;
    cudaGetSymbolAddress((void**)&a3,    g_a3);
    cudaGetSymbolAddress((void**)&w3in,  g_w3in);
    cudaGetSymbolAddress((void**)&w3out, g_w3out);
    cudaGetSymbolAddress((void**)&attn_src, g_attn);

    // 0) split conversions (weights + x)
    split_kernel<1><<<3072 * 2, 256>>>(W_in,  w3in);
    split_kernel<1><<<1024 * 2, 256>>>(W_out, w3out);
    split_kernel<0><<<4096 * 2, 256>>>(x, a3);
    // 1) QKV projection via mma.sync -> routed q/k/v
    gemm_ms<0><<<dim3(24, 32), 256>>>(b_in, nullptr);
    // 2) fused attention -> g_attn
    attn_kernel<<<dim3(16, 64), 256>>>(ab, abm, kpm);
    // 3) split attn output, then output projection
    split_kernel<0><<<4096 * 2, 256>>>(attn_src, a3);
    gemm_ms<1><<<dim3(8, 32), 256>>>(b_out, out);
}

// round 5
// speedup vs baseline: 2.3554x; 1.6239x over previous
#include <cuda_runtime.h>
#include <cuda_bf16.h>
#include <cstdint>
#include <cstddef>

// Problem constants: S=1024, B=4, E=1024, H=16, D=64
#define S_LEN   1024
#define BATCH   4
#define NHEADS  16
#define DHEAD   64
#define NBH     64          // BATCH*NHEADS
#define NROWS   4096        // S*B
#define EMB     1024

typedef unsigned long long ull;

// ---------------- scratch (device globals; no allocation allowed) ----------
// Split-bf16 K-tripled operands for the projection GEMMs (K_eff = 3072):
//   A3 = [Ahi | Ahi | Alo],  W3 = [Whi | Wlo | Whi]
__device__ __nv_bfloat16 g_a3   [(size_t)4096 * 3072];
__device__ __nv_bfloat16 g_w3in [(size_t)3072 * 3072];
__device__ __nv_bfloat16 g_w3out[(size_t)1024 * 3072];

// q/k/v as split-bf16 planes: [bh][plane(hi=0,lo=1)][s][64]
__device__ __nv_bfloat16 g_qs[(size_t)NBH * 2 * S_LEN * DHEAD];
__device__ __nv_bfloat16 g_ks[(size_t)NBH * 2 * S_LEN * DHEAD];
__device__ __nv_bfloat16 g_vs[(size_t)NBH * 2 * S_LEN * DHEAD];

// ---------------- baseline-PTX async-copy / ldmatrix / mma -----------------
__device__ __forceinline__ uint32_t smem_u32(const void* p) {
    uint32_t a;
    asm("{ .reg .u64 t; cvta.to.shared.u64 t, %1; cvt.u32.u64 %0, t; }" : "=r"(a) : "l"(p));
    return a;
}
__device__ __forceinline__ void cp_async16(uint32_t saddr, const void* g) {
    asm volatile("cp.async.cg.shared.global [%0], [%1], 16;" :: "r"(saddr), "l"(g));
}
#define CP_COMMIT() asm volatile("cp.async.commit_group;" ::: "memory")
#define CP_WAIT0()  asm volatile("cp.async.wait_group 0;" ::: "memory")

__device__ __forceinline__ void ldsm_x4(uint32_t& r0, uint32_t& r1, uint32_t& r2, uint32_t& r3,
                                        uint32_t addr) {
    asm volatile("ldmatrix.sync.aligned.m8n8.x4.shared.b16 {%0,%1,%2,%3}, [%4];"
                 : "=r"(r0), "=r"(r1), "=r"(r2), "=r"(r3) : "r"(addr));
}
__device__ __forceinline__ void ldsm_x4t(uint32_t& r0, uint32_t& r1, uint32_t& r2, uint32_t& r3,
                                         uint32_t addr) {
    asm volatile("ldmatrix.sync.aligned.m8n8.x4.trans.shared.b16 {%0,%1,%2,%3}, [%4];"
                 : "=r"(r0), "=r"(r1), "=r"(r2), "=r"(r3) : "r"(addr));
}
__device__ __forceinline__ void mma16816(float* c, const uint32_t* a, const uint32_t* b) {
    asm volatile("mma.sync.aligned.m16n8k16.row.col.f32.bf16.bf16.f32 "
                 "{%0,%1,%2,%3}, {%4,%5,%6,%7}, {%8,%9}, {%0,%1,%2,%3};"
                 : "+f"(c[0]), "+f"(c[1]), "+f"(c[2]), "+f"(c[3])
                 : "r"(a[0]), "r"(a[1]), "r"(a[2]), "r"(a[3]), "r"(b[0]), "r"(b[1]));
}
__device__ __forceinline__ unsigned pack_bf(__nv_bfloat16 a, __nv_bfloat16 b) {
    return (unsigned)__bfloat16_as_ushort(a) | ((unsigned)__bfloat16_as_ushort(b) << 16);
}
__device__ __forceinline__ void split2(float x, float y, unsigned& hi, unsigned& lo) {
    __nv_bfloat16 hx = __float2bfloat16(x), hy = __float2bfloat16(y);
    hi = pack_bf(hx, hy);
    lo = pack_bf(__float2bfloat16(x - __bfloat162float(hx)),
                 __float2bfloat16(y - __bfloat162float(hy)));
}

// ===========================================================================
// Split conversion: src fp32 [rows x 1024] -> dst bf16 [rows x 3072].
// STYLE 0 (activations): [hi | hi | lo].  STYLE 1 (weights): [hi | lo | hi].
// ===========================================================================
template <int STYLE>
__global__ void split_kernel(const float* __restrict__ src, __nv_bfloat16* __restrict__ dst)
{
    int idx = blockIdx.x * 256 + threadIdx.x;       // one k-pair
    int r = idx >> 9, kp = idx & 511;
    float2 v = *(const float2*)(src + (size_t)r * 1024 + kp * 2);
    unsigned hp, lp;
    split2(v.x, v.y, hp, lp);
    size_t base = (size_t)r * 3072 + kp * 2;
    *(unsigned*)(dst + base)        = hp;
    *(unsigned*)(dst + base + 1024) = (STYLE == 0) ? hp : lp;
    *(unsigned*)(dst + base + 2048) = (STYLE == 0) ? lp : hp;
}

// ===========================================================================
// mma.sync bf16 GEMM over K_eff=3072 (UNCHANGED mainloop from R4 pass).
// MODE 0: epilogue splits to g_qs/g_ks/g_vs bf16 planes (q scaled 0.125).
// MODE 1: epilogue writes fp32 Cout.
// ===========================================================================
template <int MODE>
__global__ __launch_bounds__(256, 2)
void gemm_ms(const float* __restrict__ bias, float* __restrict__ Cout)
{
    constexpr int KE = 3072;
    __shared__ __align__(16) __nv_bfloat16 sA[2][128 * 32];
    __shared__ __align__(16) __nv_bfloat16 sB[2][128 * 32];

    const __nv_bfloat16* __restrict__ A3 = g_a3;
    const __nv_bfloat16* __restrict__ B3 = (MODE == 0) ? g_w3in : g_w3out;

    const int tid = threadIdx.x;
    const int wid = tid >> 5, lane = tid & 31;
    const int wm = wid & 1, wn = wid >> 1;
    const int m0 = blockIdx.y * 128, n0 = blockIdx.x * 128;

    float c[4][4][4];
#pragma unroll
    for (int i = 0; i < 4; i++)
#pragma unroll
        for (int j = 0; j < 4; j++)
#pragma unroll
            for (int r = 0; r < 4; r++) c[i][j][r] = 0.f;

    auto loadStage = [&](int st, int k0) {
        uint32_t baseA = smem_u32(&sA[st][0]);
        uint32_t baseB = smem_u32(&sB[st][0]);
#pragma unroll
        for (int h = 0; h < 2; h++) {
            int g = tid + 256 * h;
            int row = g >> 2, gc = g & 3;
            int sw = gc ^ ((row >> 1) & 3);
            cp_async16(baseA + row * 64 + sw * 16, A3 + (size_t)(m0 + row) * KE + k0 + gc * 8);
            cp_async16(baseB + row * 64 + sw * 16, B3 + (size_t)(n0 + row) * KE + k0 + gc * 8);
        }
    };

    loadStage(0, 0);
    CP_COMMIT();

    for (int s = 0; s < KE / 32; s++) {
        CP_WAIT0();
        __syncthreads();
        if (s + 1 < KE / 32) {
            loadStage((s + 1) & 1, (s + 1) * 32);
            CP_COMMIT();
        }
        const int st = s & 1;
        const uint32_t baseA = smem_u32(&sA[st][0]);
        const uint32_t baseB = smem_u32(&sB[st][0]);

#pragma unroll
        for (int j = 0; j < 2; j++) {
            uint32_t a[4][4];
#pragma unroll
            for (int mf = 0; mf < 4; mf++) {
                int row = wm * 64 + mf * 16 + (lane & 15);
                int g = j * 2 + (lane >> 4);
                int sw = g ^ ((row >> 1) & 3);
                ldsm_x4(a[mf][0], a[mf][1], a[mf][2], a[mf][3], baseA + row * 64 + sw * 16);
            }
            uint32_t b[4][2];
#pragma unroll
            for (int p = 0; p < 2; p++) {
                int row = wn * 32 + p * 16 + (lane & 7) + ((lane >> 4) << 3);
                int g = j * 2 + ((lane >> 3) & 1);
                int sw = g ^ ((row >> 1) & 3);
                uint32_t r0, r1, r2, r3;
                ldsm_x4(r0, r1, r2, r3, baseB + row * 64 + sw * 16);
                b[p * 2][0] = r0; b[p * 2][1] = r1;
                b[p * 2 + 1][0] = r2; b[p * 2 + 1][1] = r3;
            }
#pragma unroll
            for (int mf = 0; mf < 4; mf++)
#pragma unroll
                for (int nf = 0; nf < 4; nf++)
                    mma16816(c[mf][nf], a[mf], b[nf]);
        }
        __syncthreads();
    }

    // ---- epilogue
#pragma unroll
    for (int mf = 0; mf < 4; mf++) {
#pragma unroll
        for (int nf = 0; nf < 4; nf++) {
            int n = n0 + wn * 32 + nf * 8 + (lane & 3) * 2;
            float2 bb = *(const float2*)(bias + n);
#pragma unroll
            for (int half = 0; half < 2; half++) {
                int m = m0 + wm * 64 + mf * 16 + (lane >> 2) + half * 8;
                float vx = c[mf][nf][half * 2 + 0] + bb.x;
                float vy = c[mf][nf][half * 2 + 1] + bb.y;
                if (MODE == 0) {
                    int sI = m >> 2, bI = m & 3;
                    int h = n / 192, t = n % 192;
                    size_t pb = (size_t)(bI * NHEADS + h) * 2 * 65536;
                    __nv_bfloat16* dst;
                    int d;
                    if (t < 64)      { vx *= 0.125f; vy *= 0.125f; dst = g_qs + pb; d = t; }
                    else if (t < 128){ dst = g_ks + pb; d = t - 64; }
                    else             { dst = g_vs + pb; d = t - 128; }
                    unsigned hi, lo;
                    split2(vx, vy, hi, lo);
                    *(unsigned*)(dst + (size_t)sI * 64 + d)         = hi;
                    *(unsigned*)(dst + 65536 + (size_t)sI * 64 + d) = lo;
                } else {
                    *(float2*)(Cout + (size_t)m * EMB + n) = make_float2(vx, vy);
                }
            }
        }
    }
}

// ===========================================================================
// Tensor-core fused attention. Block = 128 q rows x full 1024 keys (16x64).
// 8 warps; warp w owns q rows [16w,16w+16) -> softmax stats warp-local.
// Split-bf16: scores = Qhi.Khi + Qhi.Klo + Qlo.Khi; O += Phi.Vhi+Phi.Vlo+Plo.Vhi
// softmax_1 exact via running-max init 0 (phantom +1 = exp(-m_final)).
// V consumed with ldmatrix.trans ([key][d] storage -> [d][key] B-operand).
// Output written directly in g_a3 split [hi|hi|lo] format for gemm_ms<1>.
// SMEM 96KB dynamic: Qhi Qlo (16K ea) Khi Klo Vhi Vlo (8K ea) Phi Plo (16K ea)
// ===========================================================================
#define SM_QHI 0
#define SM_QLO 16384
#define SM_KHI 32768
#define SM_KLO 40960
#define SM_VHI 49152
#define SM_VLO 57344
#define SM_PHI 65536
#define SM_PLO 81920
#define ATT_SMEM 98304

__global__ __launch_bounds__(256, 2)
void attn_mma(const float* __restrict__ abias, const float* __restrict__ amul,
              const int* __restrict__ kpm)
{
    extern __shared__ __align__(16) char sm[];
    const uint32_t sb = smem_u32(sm);
    const int tid = threadIdx.x;
    const int w = tid >> 5, lane = tid & 31;
    const int bh = blockIdx.y;
    const int q0 = blockIdx.x * 128;
    const int bI = bh >> 4, h = bh & 15;

    const __nv_bfloat16* qsrc = g_qs + (size_t)bh * 2 * 65536;
    const __nv_bfloat16* ksrc = g_ks + (size_t)bh * 2 * 65536;
    const __nv_bfloat16* vsrc = g_vs + (size_t)bh * 2 * 65536;

    // Q planes (persist whole kernel): 2048 x 16B granules, swizzle g^(row&7)
#pragma unroll
    for (int i = 0; i < 8; i++) {
        int g = tid + 256 * i;
        int plane = g >> 10, r = (g >> 3) & 127, gc = g & 7;
        cp_async16(sb + SM_QHI + plane * 16384 + r * 128 + ((gc ^ (r & 7)) << 4),
                   qsrc + plane * 65536 + (size_t)(q0 + r) * 64 + gc * 8);
    }
    CP_COMMIT();

    float o[8][4];
#pragma unroll
    for (int i = 0; i < 8; i++)
#pragma unroll
        for (int r = 0; r < 4; r++) o[i][r] = 0.f;
    float mr0 = 0.f, mr1 = 0.f, ls0 = 0.f, ls1 = 0.f;   // running max/sum (phantom 0)

    const int rA = lane >> 2;          // 0..7: first fragment row
    const int cA = (lane & 3) * 2;     // col pair base

    for (int chunk = 0; chunk < 16; chunk++) {
        const int k0 = chunk * 64;
        __syncthreads();               // prior chunk done with K/V
#pragma unroll
        for (int i = 0; i < 8; i++) {
            int g = tid + 256 * i;
            int plane = g >> 9, r = (g >> 3) & 63, gc = g & 7;
            const __nv_bfloat16* src = (plane < 2 ? ksrc : vsrc) + (plane & 1) * 65536
                                       + (size_t)(k0 + r) * 64 + gc * 8;
            cp_async16(sb + SM_KHI + plane * 8192 + r * 128 + ((gc ^ (r & 7)) << 4), src);
        }
        CP_COMMIT(); CP_WAIT0();
        __syncthreads();

        // ---- scores: c[nf][..] = (Q.K^T) over split planes
        float c[8][4];
#pragma unroll
        for (int i = 0; i < 8; i++)
#pragma unroll
            for (int r = 0; r < 4; r++) c[i][r] = 0.f;
#pragma unroll
        for (int j = 0; j < 4; j++) {
            uint32_t aH[4], aL[4];
            {
                int r = w * 16 + (lane & 15);
                int g = j * 2 + (lane >> 4);
                int s_ = g ^ (r & 7);
                ldsm_x4(aH[0], aH[1], aH[2], aH[3], sb + SM_QHI + r * 128 + s_ * 16);
                ldsm_x4(aL[0], aL[1], aL[2], aL[3], sb + SM_QLO + r * 128 + s_ * 16);
            }
#pragma unroll
            for (int p = 0; p < 4; p++) {
                int r = p * 16 + (lane & 7) + ((lane >> 4) << 3);
                int g = j * 2 + ((lane >> 3) & 1);
                int s_ = g ^ (r & 7);
                uint32_t b0, b1, b2, b3, bb[2];
                ldsm_x4(b0, b1, b2, b3, sb + SM_KHI + r * 128 + s_ * 16);
                bb[0] = b0; bb[1] = b1;
                mma16816(c[2 * p], aH, bb); mma16816(c[2 * p], aL, bb);
                bb[0] = b2; bb[1] = b3;
                mma16816(c[2 * p + 1], aH, bb); mma16816(c[2 * p + 1], aL, bb);
                ldsm_x4(b0, b1, b2, b3, sb + SM_KLO + r * 128 + s_ * 16);
                bb[0] = b0; bb[1] = b1; mma16816(c[2 * p], aH, bb);
                bb[0] = b2; bb[1] = b3; mma16816(c[2 * p + 1], aH, bb);
            }
        }

        // ---- softmax pass 1: + bias, mask, chunk row-max
        const int qg0 = q0 + w * 16 + rA;
        const size_t bo0 = ((size_t)bh * S_LEN + qg0) * S_LEN + k0 + cA;
        const size_t bo1 = bo0 + (size_t)8 * S_LEN;
        float cm0 = -1e30f, cm1 = -1e30f;
#pragma unroll
        for (int nf = 0; nf < 8; nf++) {
            int2 mk = __ldg((const int2*)(kpm + bI * S_LEN + k0 + nf * 8 + cA));
            float2 bA = __ldg((const float2*)(abias + bo0 + nf * 8));
            float2 bB = __ldg((const float2*)(abias + bo1 + nf * 8));
            c[nf][0] += bA.x; c[nf][1] += bA.y; c[nf][2] += bB.x; c[nf][3] += bB.y;
            if (mk.x) { c[nf][0] = -1e30f; c[nf][2] = -1e30f; }
            if (mk.y) { c[nf][1] = -1e30f; c[nf][3] = -1e30f; }
            cm0 = fmaxf(cm0, fmaxf(c[nf][0], c[nf][1]));
            cm1 = fmaxf(cm1, fmaxf(c[nf][2], c[nf][3]));
        }
        cm0 = fmaxf(cm0, __shfl_xor_sync(0xffffffffu, cm0, 1));
        cm0 = fmaxf(cm0, __shfl_xor_sync(0xffffffffu, cm0, 2));
        cm1 = fmaxf(cm1, __shfl_xor_sync(0xffffffffu, cm1, 1));
        cm1 = fmaxf(cm1, __shfl_xor_sync(0xffffffffu, cm1, 2));
        float nm0 = fmaxf(mr0, cm0), nm1 = fmaxf(mr1, cm1);
        float al0 = __expf(mr0 - nm0), al1 = __expf(mr1 - nm1);
        mr0 = nm0; mr1 = nm1;

        // ---- pass 2: exp, *mul, split-store P; accumulate l
        float s0 = 0.f, s1 = 0.f;
        const int r0 = w * 16 + rA, r1 = r0 + 8;
#pragma unroll
        for (int nf = 0; nf < 8; nf++) {
            float2 mA = __ldg((const float2*)(amul + bo0 + nf * 8));
            float2 mB = __ldg((const float2*)(amul + bo1 + nf * 8));
            float e0 = __expf(c[nf][0] - nm0), e1 = __expf(c[nf][1] - nm0);
            float e2 = __expf(c[nf][2] - nm1), e3 = __expf(c[nf][3] - nm1);
            s0 += e0 + e1; s1 += e2 + e3;
            // masked cols: e == 0 exactly -> p == 0 regardless of mul
            float p0 = e0 * mA.x, p1 = e1 * mA.y, p2 = e2 * mB.x, p3 = e3 * mB.y;
            int col = nf * 8 + cA;
            int gc = col >> 3, cb = (col & 7) * 2;
            unsigned hi, lo;
            split2(p0, p1, hi, lo);
            *(unsigned*)(sm + SM_PHI + r0 * 128 + ((gc ^ (r0 & 7)) << 4) + cb) = hi;
            *(unsigned*)(sm + SM_PLO + r0 * 128 + ((gc ^ (r0 & 7)) << 4) + cb) = lo;
            split2(p2, p3, hi, lo);
            *(unsigned*)(sm + SM_PHI + r1 * 128 + ((gc ^ (r1 & 7)) << 4) + cb) = hi;
            *(unsigned*)(sm + SM_PLO + r1 * 128 + ((gc ^ (r1 & 7)) << 4) + cb) = lo;
        }
        ls0 = ls0 * al0 + s0;
        ls1 = ls1 * al1 + s1;
#pragma unroll
        for (int nf = 0; nf < 8; nf++) {
            o[nf][0] *= al0; o[nf][1] *= al0;
            o[nf][2] *= al1; o[nf][3] *= al1;
        }
        __syncwarp();   // P rows are warp-private; warp-level visibility suffices

        // ---- O += P.V (ldmatrix.trans for V)
#pragma unroll
        for (int j = 0; j < 4; j++) {
            uint32_t aH[4], aL[4];
            {
                int r = w * 16 + (lane & 15);
                int g = j * 2 + (lane >> 4);
                int s_ = g ^ (r & 7);
                ldsm_x4(aH[0], aH[1], aH[2], aH[3], sb + SM_PHI + r * 128 + s_ * 16);
                ldsm_x4(aL[0], aL[1], aL[2], aL[3], sb + SM_PLO + r * 128 + s_ * 16);
            }
#pragma unroll
            for (int p = 0; p < 4; p++) {
                int kr = j * 16 + ((lane >> 3) & 1) * 8 + (lane & 7);
                int g = p * 2 + ((lane >> 4) & 1);
                int s_ = g ^ (kr & 7);
                uint32_t b0, b1, b2, b3, bb[2];
                ldsm_x4t(b0, b1, b2, b3, sb + SM_VHI + kr * 128 + s_ * 16);
                bb[0] = b0; bb[1] = b1;
                mma16816(o[2 * p], aH, bb); mma16816(o[2 * p], aL, bb);
                bb[0] = b2; bb[1] = b3;
                mma16816(o[2 * p + 1], aH, bb); mma16816(o[2 * p + 1], aL, bb);
                ldsm_x4t(b0, b1, b2, b3, sb + SM_VLO + kr * 128 + s_ * 16);
                bb[0] = b0; bb[1] = b1; mma16816(o[2 * p], aH, bb);
                bb[0] = b2; bb[1] = b3; mma16816(o[2 * p + 1], aH, bb);
            }
        }
    }

    // ---- finalize: denom = exp(-m) + sum(e); write g_a3 [hi|hi|lo]
    ls0 += __shfl_xor_sync(0xffffffffu, ls0, 1);
    ls0 += __shfl_xor_sync(0xffffffffu, ls0, 2);
    ls1 += __shfl_xor_sync(0xffffffffu, ls1, 1);
    ls1 += __shfl_xor_sync(0xffffffffu, ls1, 2);
    float inv0 = 1.0f / (__expf(-mr0) + ls0);
    float inv1 = 1.0f / (__expf(-mr1) + ls1);
    const int row0 = (q0 + w * 16 + rA) * BATCH + bI;
    const int row1 = (q0 + w * 16 + rA + 8) * BATCH + bI;
#pragma unroll
    for (int nf = 0; nf < 8; nf++) {
        int col = h * 64 + nf * 8 + cA;
        unsigned hi, lo;
        split2(o[nf][0] * inv0, o[nf][1] * inv0, hi, lo);
        *(unsigned*)(g_a3 + (size_t)row0 * 3072 + col)        = hi;
        *(unsigned*)(g_a3 + (size_t)row0 * 3072 + 1024 + col) = hi;
        *(unsigned*)(g_a3 + (size_t)row0 * 3072 + 2048 + col) = lo;
        split2(o[nf][2] * inv1, o[nf][3] * inv1, hi, lo);
        *(unsigned*)(g_a3 + (size_t)row1 * 3072 + col)        = hi;
        *(unsigned*)(g_a3 + (size_t)row1 * 3072 + 1024 + col) = hi;
        *(unsigned*)(g_a3 + (size_t)row1 * 3072 + 2048 + col) = lo;
    }
}

// ===========================================================================
extern "C" void kernel_launch(void* const* d_in, const int* in_sizes, int n_in,
                              void* d_out, int out_size)
{
    const float* x     = (const float*)d_in[0];
    const float* ab    = (const float*)d_in[1];
    const float* abm   = (const float*)d_in[2];
    const int*   kpm   = (const int*)d_in[3];
    const float* W_in  = (const float*)d_in[4];
    const float* b_in  = (const float*)d_in[5];
    const float* W_out = (const float*)d_in[6];
    const float* b_out = (const float*)d_in[7];
    float* out = (float*)d_out;

    __nv_bfloat16 *a3, *w3in, *w3out;
    cudaGetSymbolAddress((void**)&a3,    g_a3);
    cudaGetSymbolAddress((void**)&w3in,  g_w3in);
    cudaGetSymbolAddress((void**)&w3out, g_w3out);

    cudaFuncSetAttribute(attn_mma, cudaFuncAttributeMaxDynamicSharedMemorySize, ATT_SMEM);

    // 0) split conversions (weights + x)
    split_kernel<1><<<3072 * 2, 256>>>(W_in,  w3in);
    split_kernel<1><<<1024 * 2, 256>>>(W_out, w3out);
    split_kernel<0><<<4096 * 2, 256>>>(x, a3);
    // 1) QKV projection -> split q/k/v planes
    gemm_ms<0><<<dim3(24, 32), 256>>>(b_in, nullptr);
    // 2) tensor-core fused attention -> g_a3 (split format)
    attn_mma<<<dim3(8, NBH), 256, ATT_SMEM>>>(ab, abm, kpm);
    // 3) output projection
    gemm_ms<1><<<dim3(8, 32), 256>>>(b_out, out);
}